// round 1
// baseline (speedup 1.0000x reference)
#include <cuda_runtime.h>
#include <math.h>

#define H    1024
#define SQ   2048
#define BB   2
#define NH   16
#define HD   64
#define TH   3072          // 3*H
#define ROWS 4096          // BB*SQ
#define EPSV 1e-5f

// ---------------- scratch (device globals; allocation-free) ----------------
__device__ float g_mod[BB * TH];                 // [B, 3H] : scale | shift | gate
__device__ float g_h  [ROWS * H];                // modulated LN output
__device__ float g_qkv[(size_t)ROWS * TH];       // qkv projection (q,k rewritten in place)
__device__ float g_o  [ROWS * H];                // attention output (B,S,H layout)

// ---------------- kernel 1: mod = silu(ada) @ mod_w^T + mod_b --------------
__global__ void mod_kernel(const float* __restrict__ ada,
                           const float* __restrict__ mw,
                           const float* __restrict__ mb) {
    int o = blockIdx.x;          // 0..3071
    int b = blockIdx.y;          // 0..1
    int t = threadIdx.x;         // 128 threads
    const float* a = ada + b * H;
    const float* w = mw + (size_t)o * H;
    float s = 0.f;
    for (int j = t; j < H; j += 128) {
        float av = a[j];
        float si = av / (1.f + expf(-av));
        s += si * w[j];
    }
    __shared__ float red[128];
    red[t] = s; __syncthreads();
    for (int st = 64; st > 0; st >>= 1) {
        if (t < st) red[t] += red[t + st];
        __syncthreads();
    }
    if (t == 0) g_mod[b * TH + o] = red[0] + mb[o];
}

// ------------- kernel 2: h = LN(x)*ln_w*(scale+1)+shift --------------------
__global__ void ln_mod_kernel(const float* __restrict__ x,
                              const float* __restrict__ lnw) {
    int row = blockIdx.x;                // 0..4095
    int t   = threadIdx.x;               // 256 threads
    int b   = row >> 11;
    const float* xr = x + (size_t)row * H;
    float v[4]; float s = 0.f, ss = 0.f;
#pragma unroll
    for (int i = 0; i < 4; i++) {
        v[i] = xr[t + i * 256];
        s += v[i]; ss += v[i] * v[i];
    }
    __shared__ float rs[256], rq[256];
    rs[t] = s; rq[t] = ss; __syncthreads();
    for (int st = 128; st > 0; st >>= 1) {
        if (t < st) { rs[t] += rs[t + st]; rq[t] += rq[t + st]; }
        __syncthreads();
    }
    float mean = rs[0] * (1.f / H);
    float var  = rq[0] * (1.f / H) - mean * mean;
    float rstd = rsqrtf(var + EPSV);
    const float* scale = g_mod + b * TH;      // [0:H)
    const float* shift = scale + H;           // [H:2H)
    float* hr = g_h + (size_t)row * H;
#pragma unroll
    for (int i = 0; i < 4; i++) {
        int c = t + i * 256;
        hr[c] = (v[i] - mean) * rstd * lnw[c] * (scale[c] + 1.f) + shift[c];
    }
}

// ------------- kernel 3/6: SGEMM NT  C[M,N] = A[M,K] @ B[N,K]^T ------------
// optional gate epilogue: C[m,n] *= g_mod[(m/2048)*3H + 2H + n]  (N==H case)
__global__ __launch_bounds__(256, 2)
void sgemm_nt(const float* __restrict__ A, const float* __restrict__ Bm,
              float* __restrict__ C, int M, int N, int K, int useGate) {
    __shared__ float As[8][128];
    __shared__ float Bs[8][128];
    int tid = threadIdx.x;
    int ty = tid >> 4, tx = tid & 15;
    int rowBase = blockIdx.y * 128, colBase = blockIdx.x * 128;
    int lrow = tid >> 1, lk4 = (tid & 1) * 4;
    const float* Ag = A  + (size_t)(rowBase + lrow) * K + lk4;
    const float* Bg = Bm + (size_t)(colBase + lrow) * K + lk4;

    float acc[8][8];
#pragma unroll
    for (int i = 0; i < 8; i++)
#pragma unroll
        for (int j = 0; j < 8; j++) acc[i][j] = 0.f;

    for (int k0 = 0; k0 < K; k0 += 8) {
        float4 av = *(const float4*)(Ag + k0);
        float4 bv = *(const float4*)(Bg + k0);
        As[lk4 + 0][lrow] = av.x; As[lk4 + 1][lrow] = av.y;
        As[lk4 + 2][lrow] = av.z; As[lk4 + 3][lrow] = av.w;
        Bs[lk4 + 0][lrow] = bv.x; Bs[lk4 + 1][lrow] = bv.y;
        Bs[lk4 + 2][lrow] = bv.z; Bs[lk4 + 3][lrow] = bv.w;
        __syncthreads();
#pragma unroll
        for (int k = 0; k < 8; k++) {
            float4 a0 = *(const float4*)&As[k][ty * 8];
            float4 a1 = *(const float4*)&As[k][ty * 8 + 4];
            float4 b0 = *(const float4*)&Bs[k][tx * 8];
            float4 b1 = *(const float4*)&Bs[k][tx * 8 + 4];
            float a[8] = {a0.x, a0.y, a0.z, a0.w, a1.x, a1.y, a1.z, a1.w};
            float bb[8] = {b0.x, b0.y, b0.z, b0.w, b1.x, b1.y, b1.z, b1.w};
#pragma unroll
            for (int i = 0; i < 8; i++)
#pragma unroll
                for (int j = 0; j < 8; j++)
                    acc[i][j] += a[i] * bb[j];
        }
        __syncthreads();
    }
#pragma unroll
    for (int i = 0; i < 8; i++) {
        int m = rowBase + ty * 8 + i;
        float* Crow = C + (size_t)m * N + colBase + tx * 8;
        if (useGate) {
            const float* gp = g_mod + (m >> 11) * TH + 2 * H + colBase + tx * 8;
#pragma unroll
            for (int j = 0; j < 8; j++) Crow[j] = acc[i][j] * gp[j];
        } else {
#pragma unroll
            for (int j = 0; j < 8; j++) Crow[j] = acc[i][j];
        }
    }
}

// ------------- kernel 4: per-head QK layernorm + RoPE (in place) -----------
__global__ void qkln_rope_kernel(const float* __restrict__ freqs,
                                 const float* __restrict__ qnw,
                                 const float* __restrict__ knw) {
    int gw   = blockIdx.x * 8 + (threadIdx.x >> 5);   // global warp id
    int lane = threadIdx.x & 31;
    int head = gw & 15;
    int row  = (gw >> 4) & 4095;
    int qk   = gw >> 16;                              // 0 = q, 1 = k

    float* p = g_qkv + (size_t)row * TH + qk * H + head * HD;
    const float* w = qk ? knw : qnw;

    float v0 = p[lane], v1 = p[lane + 32];
    float s = v0 + v1;
#pragma unroll
    for (int off = 16; off > 0; off >>= 1) s += __shfl_xor_sync(0xffffffffu, s, off);
    float mean = s * (1.f / 64.f);
    float d0 = v0 - mean, d1 = v1 - mean;
    float vs = d0 * d0 + d1 * d1;
#pragma unroll
    for (int off = 16; off > 0; off >>= 1) vs += __shfl_xor_sync(0xffffffffu, vs, off);
    float rstd = rsqrtf(vs * (1.f / 64.f) + EPSV);
    float n0 = d0 * rstd * w[lane];
    float n1 = d1 * rstd * w[lane + 32];

    int sIdx = row & 2047;
    const float* f = freqs + (size_t)sIdx * 64;       // [32 pairs][2]
    // slot 0: element = lane, pair index = lane>>1
    float f0a = f[(lane >> 1) * 2 + 0], f1a = f[(lane >> 1) * 2 + 1];
    float part0 = __shfl_xor_sync(0xffffffffu, n0, 1);
    float r0 = (lane & 1) ? (n0 * f0a + part0 * f1a) : (n0 * f0a - part0 * f1a);
    // slot 1: element = 32+lane, pair index = 16 + (lane>>1)
    float f0b = f[(16 + (lane >> 1)) * 2 + 0], f1b = f[(16 + (lane >> 1)) * 2 + 1];
    float part1 = __shfl_xor_sync(0xffffffffu, n1, 1);
    float r1 = (lane & 1) ? (n1 * f0b + part1 * f1b) : (n1 * f0b - part1 * f1b);

    p[lane] = r0;
    p[lane + 32] = r1;
}

// ------------- kernel 5: flash attention fp32 (BM=64, BN=32) ---------------
__global__ __launch_bounds__(256)
void flash_kernel() {
    __shared__ float Qs[64 * 65];
    __shared__ float Ks[32 * 65];
    __shared__ float Vs[32 * 64];
    __shared__ float Ps[64 * 33];

    int qt = blockIdx.x;          // 0..31 query tiles of 64
    int h  = blockIdx.y;          // head
    int b  = blockIdx.z;          // batch
    int tid = threadIdx.x;
    int ty = tid >> 4, tx = tid & 15;

    const float* qbase = g_qkv + (size_t)(b * SQ) * TH + h * HD;
    const float* kbase = qbase + H;
    const float* vbase = qbase + 2 * H;

    // load Q tile (64 rows x 64 dims)
    for (int e4 = tid; e4 < 64 * 16; e4 += 256) {
        int r = e4 >> 4, d4 = (e4 & 15) * 4;
        float4 v = *(const float4*)(qbase + (size_t)(qt * 64 + r) * TH + d4);
        float* q = &Qs[r * 65 + d4];
        q[0] = v.x; q[1] = v.y; q[2] = v.z; q[3] = v.w;
    }

    float o[4][4];
    float mrow[4], lrow[4];
#pragma unroll
    for (int i = 0; i < 4; i++) {
        mrow[i] = -3.0e38f; lrow[i] = 0.f;
#pragma unroll
        for (int j = 0; j < 4; j++) o[i][j] = 0.f;
    }

    for (int kt = 0; kt < 64; kt++) {
        // load K,V tiles (32 rows x 64 dims each)
        for (int e4 = tid; e4 < 32 * 16; e4 += 256) {
            int r = e4 >> 4, d4 = (e4 & 15) * 4;
            float4 kv = *(const float4*)(kbase + (size_t)(kt * 32 + r) * TH + d4);
            float* ks = &Ks[r * 65 + d4];
            ks[0] = kv.x; ks[1] = kv.y; ks[2] = kv.z; ks[3] = kv.w;
            float4 vv = *(const float4*)(vbase + (size_t)(kt * 32 + r) * TH + d4);
            *(float4*)&Vs[r * 64 + d4] = vv;
        }
        __syncthreads();

        // S = Q K^T (per-thread 4 rows x 2 cols)
        float sfr[4][2] = {{0.f,0.f},{0.f,0.f},{0.f,0.f},{0.f,0.f}};
#pragma unroll 16
        for (int d = 0; d < 64; d++) {
            float a0 = Qs[(ty * 4 + 0) * 65 + d];
            float a1 = Qs[(ty * 4 + 1) * 65 + d];
            float a2 = Qs[(ty * 4 + 2) * 65 + d];
            float a3 = Qs[(ty * 4 + 3) * 65 + d];
            float b0 = Ks[(tx * 2 + 0) * 65 + d];
            float b1 = Ks[(tx * 2 + 1) * 65 + d];
            sfr[0][0] += a0 * b0; sfr[0][1] += a0 * b1;
            sfr[1][0] += a1 * b0; sfr[1][1] += a1 * b1;
            sfr[2][0] += a2 * b0; sfr[2][1] += a2 * b1;
            sfr[3][0] += a3 * b0; sfr[3][1] += a3 * b1;
        }

        // online softmax (row groups: 16 threads sharing ty, within 16-lane half)
#pragma unroll
        for (int i = 0; i < 4; i++) {
            float s0 = sfr[i][0] * 0.125f, s1 = sfr[i][1] * 0.125f;
            float tmax = fmaxf(s0, s1);
#pragma unroll
            for (int off = 8; off > 0; off >>= 1)
                tmax = fmaxf(tmax, __shfl_xor_sync(0xffffffffu, tmax, off));
            float mnew = fmaxf(mrow[i], tmax);
            float corr = __expf(mrow[i] - mnew);
            float p0 = __expf(s0 - mnew);
            float p1 = __expf(s1 - mnew);
            float rsum = p0 + p1;
#pragma unroll
            for (int off = 8; off > 0; off >>= 1)
                rsum += __shfl_xor_sync(0xffffffffu, rsum, off);
            lrow[i] = lrow[i] * corr + rsum;
            mrow[i] = mnew;
#pragma unroll
            for (int jj = 0; jj < 4; jj++) o[i][jj] *= corr;
            Ps[(ty * 4 + i) * 33 + tx * 2 + 0] = p0;
            Ps[(ty * 4 + i) * 33 + tx * 2 + 1] = p1;
        }
        __syncthreads();

        // O += P V (per-thread 4 rows x 4 dims)
#pragma unroll 8
        for (int j = 0; j < 32; j++) {
            float p0 = Ps[(ty * 4 + 0) * 33 + j];
            float p1 = Ps[(ty * 4 + 1) * 33 + j];
            float p2 = Ps[(ty * 4 + 2) * 33 + j];
            float p3 = Ps[(ty * 4 + 3) * 33 + j];
            float v0 = Vs[j * 64 + tx * 4 + 0];
            float v1 = Vs[j * 64 + tx * 4 + 1];
            float v2 = Vs[j * 64 + tx * 4 + 2];
            float v3 = Vs[j * 64 + tx * 4 + 3];
            o[0][0] += p0 * v0; o[0][1] += p0 * v1; o[0][2] += p0 * v2; o[0][3] += p0 * v3;
            o[1][0] += p1 * v0; o[1][1] += p1 * v1; o[1][2] += p1 * v2; o[1][3] += p1 * v3;
            o[2][0] += p2 * v0; o[2][1] += p2 * v1; o[2][2] += p2 * v2; o[2][3] += p2 * v3;
            o[3][0] += p3 * v0; o[3][1] += p3 * v1; o[3][2] += p3 * v2; o[3][3] += p3 * v3;
        }
        __syncthreads();
    }

    // epilogue: normalize and write to [B,S,H] layout
#pragma unroll
    for (int i = 0; i < 4; i++) {
        float inv = 1.f / lrow[i];
        int grow = b * SQ + qt * 64 + ty * 4 + i;
        float* op = g_o + (size_t)grow * H + h * HD + tx * 4;
#pragma unroll
        for (int jj = 0; jj < 4; jj++) op[jj] = o[i][jj] * inv;
    }
}

// ----------------------------- launch ------------------------------------
extern "C" void kernel_launch(void* const* d_in, const int* in_sizes, int n_in,
                              void* d_out, int out_size) {
    const float* x     = (const float*)d_in[0];
    const float* ada   = (const float*)d_in[1];
    const float* freqs = (const float*)d_in[2];
    const float* w_qkv = (const float*)d_in[3];
    const float* w_o   = (const float*)d_in[4];
    const float* ln_w  = (const float*)d_in[5];
    const float* mod_w = (const float*)d_in[6];
    const float* mod_b = (const float*)d_in[7];
    const float* qn_w  = (const float*)d_in[8];
    const float* kn_w  = (const float*)d_in[9];
    float* out = (float*)d_out;

    void *hp, *qkvp, *op;
    cudaGetSymbolAddress(&hp,   g_h);
    cudaGetSymbolAddress(&qkvp, g_qkv);
    cudaGetSymbolAddress(&op,   g_o);

    mod_kernel<<<dim3(TH, BB), 128>>>(ada, mod_w, mod_b);
    ln_mod_kernel<<<ROWS, 256>>>(x, ln_w);
    sgemm_nt<<<dim3(TH / 128, ROWS / 128), 256>>>(
        (const float*)hp, w_qkv, (float*)qkvp, ROWS, TH, H, 0);
    qkln_rope_kernel<<<(2 * ROWS * NH) / 8, 256>>>(freqs, qn_w, kn_w);
    flash_kernel<<<dim3(SQ / 64, NH, BB), 256>>>();
    sgemm_nt<<<dim3(H / 128, ROWS / 128), 256>>>(
        (const float*)op, w_o, out, ROWS, H, H, 1);
}

// round 2
// speedup vs baseline: 2.0134x; 2.0134x over previous
#include <cuda_runtime.h>
#include <math.h>
#include <stdint.h>

#define H    1024
#define SQ   2048
#define BB   2
#define NH   16
#define HD   64
#define TH   3072          // 3*H
#define ROWS 4096          // BB*SQ
#define EPSV 1e-5f

// ---------------- scratch (device globals; allocation-free) ----------------
__device__ float g_mod[BB * TH];                 // [B, 3H] : scale | shift | gate
__device__ float g_h  [ROWS * H];                // modulated LN output
__device__ float g_qkv[(size_t)ROWS * TH];       // qkv projection (q,k rewritten in place)
__device__ float g_o  [ROWS * H];                // attention output (B,S,H layout)

// ---------------- tf32 helpers ---------------------------------------------
__device__ __forceinline__ float to_tf32(float v) {
    uint32_t t;
    asm("cvt.rna.tf32.f32 %0, %1;" : "=r"(t) : "f"(v));
    return __uint_as_float(t);
}
__device__ __forceinline__ void mma_tf32(float c[4],
                                         uint32_t a0, uint32_t a1, uint32_t a2, uint32_t a3,
                                         uint32_t b0, uint32_t b1) {
    asm volatile("mma.sync.aligned.m16n8k8.row.col.f32.tf32.tf32.f32 "
                 "{%0,%1,%2,%3},{%4,%5,%6,%7},{%8,%9},{%0,%1,%2,%3};"
                 : "+f"(c[0]), "+f"(c[1]), "+f"(c[2]), "+f"(c[3])
                 : "r"(a0), "r"(a1), "r"(a2), "r"(a3), "r"(b0), "r"(b1));
}
#define FB(x) __float_as_uint(x)

// ---------------- kernel 1: mod = silu(ada) @ mod_w^T + mod_b --------------
__global__ void mod_kernel(const float* __restrict__ ada,
                           const float* __restrict__ mw,
                           const float* __restrict__ mb) {
    int o = blockIdx.x;
    int b = blockIdx.y;
    int t = threadIdx.x;         // 128 threads
    const float* a = ada + b * H;
    const float* w = mw + (size_t)o * H;
    float s = 0.f;
    for (int j = t; j < H; j += 128) {
        float av = a[j];
        float si = av / (1.f + expf(-av));
        s += si * w[j];
    }
    __shared__ float red[128];
    red[t] = s; __syncthreads();
    for (int st = 64; st > 0; st >>= 1) {
        if (t < st) red[t] += red[t + st];
        __syncthreads();
    }
    if (t == 0) g_mod[b * TH + o] = red[0] + mb[o];
}

// ------------- kernel 2: h = LN(x)*ln_w*(scale+1)+shift --------------------
__global__ void ln_mod_kernel(const float* __restrict__ x,
                              const float* __restrict__ lnw) {
    int row = blockIdx.x;
    int t   = threadIdx.x;               // 256 threads
    int b   = row >> 11;
    const float* xr = x + (size_t)row * H;
    float v[4]; float s = 0.f, ss = 0.f;
#pragma unroll
    for (int i = 0; i < 4; i++) {
        v[i] = xr[t + i * 256];
        s += v[i]; ss += v[i] * v[i];
    }
    __shared__ float rs[256], rq[256];
    rs[t] = s; rq[t] = ss; __syncthreads();
    for (int st = 128; st > 0; st >>= 1) {
        if (t < st) { rs[t] += rs[t + st]; rq[t] += rq[t + st]; }
        __syncthreads();
    }
    float mean = rs[0] * (1.f / H);
    float var  = rq[0] * (1.f / H) - mean * mean;
    float rstd = rsqrtf(var + EPSV);
    const float* scale = g_mod + b * TH;
    const float* shift = scale + H;
    float* hr = g_h + (size_t)row * H;
#pragma unroll
    for (int i = 0; i < 4; i++) {
        int c = t + i * 256;
        hr[c] = (v[i] - mean) * rstd * lnw[c] * (scale[c] + 1.f) + shift[c];
    }
}

// ------------- tf32 MMA GEMM NT: C[M,N] = A[M,K] @ B[N,K]^T ----------------
// BM=BN=128, BK=16, 256 threads, 8 warps in 2x4, warp tile 64x32.
// optional gate epilogue: C[m,n] *= g_mod[(m>>11)*3H + 2H + n]
__global__ __launch_bounds__(256)
void gemm_tf32(const float* __restrict__ A, const float* __restrict__ Bm,
               float* __restrict__ C, int M, int N, int K, int useGate) {
    __shared__ float As[16][136];
    __shared__ float Bs[16][136];
    int tid  = threadIdx.x;
    int warp = tid >> 5, lane = tid & 31;
    int g = lane >> 2, tg = lane & 3;
    int wm = (warp >> 2) * 64, wn = (warp & 3) * 32;
    int rowBase = blockIdx.y * 128, colBase = blockIdx.x * 128;

    float acc[4][4][4];
#pragma unroll
    for (int mi = 0; mi < 4; mi++)
#pragma unroll
        for (int ni = 0; ni < 4; ni++)
#pragma unroll
            for (int r = 0; r < 4; r++) acc[mi][ni][r] = 0.f;

    int lr = tid >> 2;            // 0..63
    int lk = (tid & 3) * 4;       // 0,4,8,12
    const float* Ag = A  + (size_t)(rowBase + lr) * K + lk;
    const float* Bg = Bm + (size_t)(colBase + lr) * K + lk;

    for (int k0 = 0; k0 < K; k0 += 16) {
        float4 av0 = *(const float4*)(Ag + k0);
        float4 av1 = *(const float4*)(Ag + (size_t)64 * K + k0);
        float4 bv0 = *(const float4*)(Bg + k0);
        float4 bv1 = *(const float4*)(Bg + (size_t)64 * K + k0);
        __syncthreads();
        As[lk + 0][lr] = to_tf32(av0.x); As[lk + 1][lr] = to_tf32(av0.y);
        As[lk + 2][lr] = to_tf32(av0.z); As[lk + 3][lr] = to_tf32(av0.w);
        As[lk + 0][lr + 64] = to_tf32(av1.x); As[lk + 1][lr + 64] = to_tf32(av1.y);
        As[lk + 2][lr + 64] = to_tf32(av1.z); As[lk + 3][lr + 64] = to_tf32(av1.w);
        Bs[lk + 0][lr] = to_tf32(bv0.x); Bs[lk + 1][lr] = to_tf32(bv0.y);
        Bs[lk + 2][lr] = to_tf32(bv0.z); Bs[lk + 3][lr] = to_tf32(bv0.w);
        Bs[lk + 0][lr + 64] = to_tf32(bv1.x); Bs[lk + 1][lr + 64] = to_tf32(bv1.y);
        Bs[lk + 2][lr + 64] = to_tf32(bv1.z); Bs[lk + 3][lr + 64] = to_tf32(bv1.w);
        __syncthreads();
#pragma unroll
        for (int ks = 0; ks < 2; ks++) {
            int kk = ks * 8;
            uint32_t ar[4][4];
#pragma unroll
            for (int mi = 0; mi < 4; mi++) {
                int m = wm + mi * 16;
                ar[mi][0] = FB(As[kk + tg    ][m + g    ]);
                ar[mi][1] = FB(As[kk + tg    ][m + g + 8]);
                ar[mi][2] = FB(As[kk + tg + 4][m + g    ]);
                ar[mi][3] = FB(As[kk + tg + 4][m + g + 8]);
            }
#pragma unroll
            for (int ni = 0; ni < 4; ni++) {
                int n = wn + ni * 8;
                uint32_t b0 = FB(Bs[kk + tg    ][n + g]);
                uint32_t b1 = FB(Bs[kk + tg + 4][n + g]);
#pragma unroll
                for (int mi = 0; mi < 4; mi++)
                    mma_tf32(acc[mi][ni], ar[mi][0], ar[mi][1], ar[mi][2], ar[mi][3], b0, b1);
            }
        }
    }

#pragma unroll
    for (int mi = 0; mi < 4; mi++) {
#pragma unroll
        for (int ni = 0; ni < 4; ni++) {
            int m0 = rowBase + wm + mi * 16 + g;
            int n  = colBase + wn + ni * 8 + 2 * tg;
            if (useGate) {
                const float* gp0 = g_mod + (m0 >> 11) * TH + 2 * H + n;
                C[(size_t)m0 * N + n]           = acc[mi][ni][0] * gp0[0];
                C[(size_t)m0 * N + n + 1]       = acc[mi][ni][1] * gp0[1];
                const float* gp1 = g_mod + ((m0 + 8) >> 11) * TH + 2 * H + n;
                C[(size_t)(m0 + 8) * N + n]     = acc[mi][ni][2] * gp1[0];
                C[(size_t)(m0 + 8) * N + n + 1] = acc[mi][ni][3] * gp1[1];
            } else {
                C[(size_t)m0 * N + n]           = acc[mi][ni][0];
                C[(size_t)m0 * N + n + 1]       = acc[mi][ni][1];
                C[(size_t)(m0 + 8) * N + n]     = acc[mi][ni][2];
                C[(size_t)(m0 + 8) * N + n + 1] = acc[mi][ni][3];
            }
        }
    }
}

// ------------- kernel 4: per-head QK layernorm + RoPE (in place) -----------
__global__ void qkln_rope_kernel(const float* __restrict__ freqs,
                                 const float* __restrict__ qnw,
                                 const float* __restrict__ knw) {
    int gw   = blockIdx.x * 8 + (threadIdx.x >> 5);
    int lane = threadIdx.x & 31;
    int head = gw & 15;
    int row  = (gw >> 4) & 4095;
    int qk   = gw >> 16;

    float* p = g_qkv + (size_t)row * TH + qk * H + head * HD;
    const float* w = qk ? knw : qnw;

    float v0 = p[lane], v1 = p[lane + 32];
    float s = v0 + v1;
#pragma unroll
    for (int off = 16; off > 0; off >>= 1) s += __shfl_xor_sync(0xffffffffu, s, off);
    float mean = s * (1.f / 64.f);
    float d0 = v0 - mean, d1 = v1 - mean;
    float vs = d0 * d0 + d1 * d1;
#pragma unroll
    for (int off = 16; off > 0; off >>= 1) vs += __shfl_xor_sync(0xffffffffu, vs, off);
    float rstd = rsqrtf(vs * (1.f / 64.f) + EPSV);
    float n0 = d0 * rstd * w[lane];
    float n1 = d1 * rstd * w[lane + 32];

    int sIdx = row & 2047;
    const float* f = freqs + (size_t)sIdx * 64;
    float f0a = f[(lane >> 1) * 2 + 0], f1a = f[(lane >> 1) * 2 + 1];
    float part0 = __shfl_xor_sync(0xffffffffu, n0, 1);
    float r0 = (lane & 1) ? (n0 * f0a + part0 * f1a) : (n0 * f0a - part0 * f1a);
    float f0b = f[(16 + (lane >> 1)) * 2 + 0], f1b = f[(16 + (lane >> 1)) * 2 + 1];
    float part1 = __shfl_xor_sync(0xffffffffu, n1, 1);
    float r1 = (lane & 1) ? (n1 * f0b + part1 * f1b) : (n1 * f0b - part1 * f1b);

    p[lane] = r0;
    p[lane + 32] = r1;
}

// ------------- kernel 5: flash attention tf32 mma (BM=64, BN=64) -----------
// 4 warps, each owns 16 query rows. Dynamic smem:
//   Qs[64][72] (dim-major), Ks[64][72] (dim-major), Vs[64][72] (key-major),
//   Ps[64][68] (row-major P).
#define QS_STRIDE 72
#define PS_STRIDE 68
#define FLASH_SMEM ((64 * 72 * 3 + 64 * 68) * 4)

__global__ __launch_bounds__(128)
void flash_tf32() {
    extern __shared__ float sm[];
    float* Qs = sm;                       // [64][72]  Qs[d][q]
    float* Ks = sm + 64 * 72;             // [64][72]  Ks[d][key]
    float* Vs = sm + 2 * 64 * 72;         // [64][72]  Vs[key][d]
    float* Ps = sm + 3 * 64 * 72;         // [64][68]  Ps[q][key]

    int qt = blockIdx.x, h = blockIdx.y, b = blockIdx.z;
    int tid  = threadIdx.x;
    int warp = tid >> 5, lane = tid & 31;
    int g = lane >> 2, tg = lane & 3;
    int wm = warp * 16;

    const float* qbase = g_qkv + (size_t)(b * SQ) * TH + h * HD;
    const float* kbase = qbase + H;
    const float* vbase = qbase + 2 * H;

    // load Q tile (transpose to dim-major, cvt tf32)
    for (int i = tid; i < 64 * 16; i += 128) {
        int r = i >> 4, d4 = (i & 15) * 4;
        float4 v = *(const float4*)(qbase + (size_t)(qt * 64 + r) * TH + d4);
        Qs[(d4 + 0) * QS_STRIDE + r] = to_tf32(v.x);
        Qs[(d4 + 1) * QS_STRIDE + r] = to_tf32(v.y);
        Qs[(d4 + 2) * QS_STRIDE + r] = to_tf32(v.z);
        Qs[(d4 + 3) * QS_STRIDE + r] = to_tf32(v.w);
    }

    float o[8][4];
#pragma unroll
    for (int i = 0; i < 8; i++)
#pragma unroll
        for (int j = 0; j < 4; j++) o[i][j] = 0.f;
    float mrow[2] = {-3.0e38f, -3.0e38f};
    float lrow[2] = {0.f, 0.f};

    for (int kt = 0; kt < 32; kt++) {
        __syncthreads();
        for (int i = tid; i < 64 * 16; i += 128) {
            int r = i >> 4, d4 = (i & 15) * 4;
            float4 kv = *(const float4*)(kbase + (size_t)(kt * 64 + r) * TH + d4);
            Ks[(d4 + 0) * QS_STRIDE + r] = to_tf32(kv.x);
            Ks[(d4 + 1) * QS_STRIDE + r] = to_tf32(kv.y);
            Ks[(d4 + 2) * QS_STRIDE + r] = to_tf32(kv.z);
            Ks[(d4 + 3) * QS_STRIDE + r] = to_tf32(kv.w);
            float4 vv = *(const float4*)(vbase + (size_t)(kt * 64 + r) * TH + d4);
            Vs[r * QS_STRIDE + d4 + 0] = to_tf32(vv.x);
            Vs[r * QS_STRIDE + d4 + 1] = to_tf32(vv.y);
            Vs[r * QS_STRIDE + d4 + 2] = to_tf32(vv.z);
            Vs[r * QS_STRIDE + d4 + 3] = to_tf32(vv.w);
        }
        __syncthreads();

        // S = Q K^T  (warp tile 16x64, 8 n-tiles)
        float s[8][4];
#pragma unroll
        for (int i = 0; i < 8; i++)
#pragma unroll
            for (int j = 0; j < 4; j++) s[i][j] = 0.f;
#pragma unroll
        for (int k0 = 0; k0 < 64; k0 += 8) {
            uint32_t a0 = FB(Qs[(k0 + tg    ) * QS_STRIDE + wm + g    ]);
            uint32_t a1 = FB(Qs[(k0 + tg    ) * QS_STRIDE + wm + g + 8]);
            uint32_t a2 = FB(Qs[(k0 + tg + 4) * QS_STRIDE + wm + g    ]);
            uint32_t a3 = FB(Qs[(k0 + tg + 4) * QS_STRIDE + wm + g + 8]);
#pragma unroll
            for (int ni = 0; ni < 8; ni++) {
                uint32_t b0 = FB(Ks[(k0 + tg    ) * QS_STRIDE + ni * 8 + g]);
                uint32_t b1 = FB(Ks[(k0 + tg + 4) * QS_STRIDE + ni * 8 + g]);
                mma_tf32(s[ni], a0, a1, a2, a3, b0, b1);
            }
        }

        // online softmax (rows g and g+8 of this warp's 16)
        float t0 = -3.0e38f, t1 = -3.0e38f;
#pragma unroll
        for (int ni = 0; ni < 8; ni++) {
#pragma unroll
            for (int j = 0; j < 4; j++) s[ni][j] *= 0.125f;
            t0 = fmaxf(t0, fmaxf(s[ni][0], s[ni][1]));
            t1 = fmaxf(t1, fmaxf(s[ni][2], s[ni][3]));
        }
        t0 = fmaxf(t0, __shfl_xor_sync(0xffffffffu, t0, 1));
        t0 = fmaxf(t0, __shfl_xor_sync(0xffffffffu, t0, 2));
        t1 = fmaxf(t1, __shfl_xor_sync(0xffffffffu, t1, 1));
        t1 = fmaxf(t1, __shfl_xor_sync(0xffffffffu, t1, 2));
        float mn0 = fmaxf(mrow[0], t0);
        float mn1 = fmaxf(mrow[1], t1);
        float corr0 = __expf(mrow[0] - mn0);
        float corr1 = __expf(mrow[1] - mn1);
        float sum0 = 0.f, sum1 = 0.f;
#pragma unroll
        for (int ni = 0; ni < 8; ni++) {
            s[ni][0] = __expf(s[ni][0] - mn0);
            s[ni][1] = __expf(s[ni][1] - mn0);
            s[ni][2] = __expf(s[ni][2] - mn1);
            s[ni][3] = __expf(s[ni][3] - mn1);
            sum0 += s[ni][0] + s[ni][1];
            sum1 += s[ni][2] + s[ni][3];
        }
        sum0 += __shfl_xor_sync(0xffffffffu, sum0, 1);
        sum0 += __shfl_xor_sync(0xffffffffu, sum0, 2);
        sum1 += __shfl_xor_sync(0xffffffffu, sum1, 1);
        sum1 += __shfl_xor_sync(0xffffffffu, sum1, 2);
        lrow[0] = lrow[0] * corr0 + sum0;
        lrow[1] = lrow[1] * corr1 + sum1;
        mrow[0] = mn0; mrow[1] = mn1;
#pragma unroll
        for (int ni = 0; ni < 8; ni++) {
            o[ni][0] *= corr0; o[ni][1] *= corr0;
            o[ni][2] *= corr1; o[ni][3] *= corr1;
        }

        // write P (tf32) to smem, per-warp private rows
#pragma unroll
        for (int ni = 0; ni < 8; ni++) {
            int c = ni * 8 + 2 * tg;
            Ps[(wm + g    ) * PS_STRIDE + c    ] = to_tf32(s[ni][0]);
            Ps[(wm + g    ) * PS_STRIDE + c + 1] = to_tf32(s[ni][1]);
            Ps[(wm + g + 8) * PS_STRIDE + c    ] = to_tf32(s[ni][2]);
            Ps[(wm + g + 8) * PS_STRIDE + c + 1] = to_tf32(s[ni][3]);
        }
        __syncwarp();

        // O += P V
#pragma unroll
        for (int k0 = 0; k0 < 64; k0 += 8) {
            uint32_t a0 = FB(Ps[(wm + g    ) * PS_STRIDE + k0 + tg    ]);
            uint32_t a1 = FB(Ps[(wm + g + 8) * PS_STRIDE + k0 + tg    ]);
            uint32_t a2 = FB(Ps[(wm + g    ) * PS_STRIDE + k0 + tg + 4]);
            uint32_t a3 = FB(Ps[(wm + g + 8) * PS_STRIDE + k0 + tg + 4]);
#pragma unroll
            for (int nd = 0; nd < 8; nd++) {
                uint32_t b0 = FB(Vs[(k0 + tg    ) * QS_STRIDE + nd * 8 + g]);
                uint32_t b1 = FB(Vs[(k0 + tg + 4) * QS_STRIDE + nd * 8 + g]);
                mma_tf32(o[nd], a0, a1, a2, a3, b0, b1);
            }
        }
        __syncwarp();
    }

    // epilogue
    float inv0 = 1.f / lrow[0];
    float inv1 = 1.f / lrow[1];
    int grow0 = b * SQ + qt * 64 + wm + g;
#pragma unroll
    for (int nd = 0; nd < 8; nd++) {
        int d = h * HD + nd * 8 + 2 * tg;
        float* p0 = g_o + (size_t)grow0 * H + d;
        p0[0] = o[nd][0] * inv0;
        p0[1] = o[nd][1] * inv0;
        float* p1 = g_o + (size_t)(grow0 + 8) * H + d;
        p1[0] = o[nd][2] * inv1;
        p1[1] = o[nd][3] * inv1;
    }
}

// ----------------------------- launch ------------------------------------
extern "C" void kernel_launch(void* const* d_in, const int* in_sizes, int n_in,
                              void* d_out, int out_size) {
    const float* x     = (const float*)d_in[0];
    const float* ada   = (const float*)d_in[1];
    const float* freqs = (const float*)d_in[2];
    const float* w_qkv = (const float*)d_in[3];
    const float* w_o   = (const float*)d_in[4];
    const float* ln_w  = (const float*)d_in[5];
    const float* mod_w = (const float*)d_in[6];
    const float* mod_b = (const float*)d_in[7];
    const float* qn_w  = (const float*)d_in[8];
    const float* kn_w  = (const float*)d_in[9];
    float* out = (float*)d_out;

    void *hp, *qkvp, *op;
    cudaGetSymbolAddress(&hp,   g_h);
    cudaGetSymbolAddress(&qkvp, g_qkv);
    cudaGetSymbolAddress(&op,   g_o);

    cudaFuncSetAttribute(flash_tf32, cudaFuncAttributeMaxDynamicSharedMemorySize,
                         FLASH_SMEM);

    mod_kernel<<<dim3(TH, BB), 128>>>(ada, mod_w, mod_b);
    ln_mod_kernel<<<ROWS, 256>>>(x, ln_w);
    gemm_tf32<<<dim3(TH / 128, ROWS / 128), 256>>>(
        (const float*)hp, w_qkv, (float*)qkvp, ROWS, TH, H, 0);
    qkln_rope_kernel<<<(2 * ROWS * NH) / 8, 256>>>(freqs, qn_w, kn_w);
    flash_tf32<<<dim3(SQ / 64, NH, BB), 128, FLASH_SMEM>>>();
    gemm_tf32<<<dim3(H / 128, ROWS / 128), 256>>>(
        (const float*)op, w_o, out, ROWS, H, H, 1);
}